// round 1
// baseline (speedup 1.0000x reference)
#include <cuda_runtime.h>

#define BATCH 32
#define HW    3136
#define C     256
#define CR    64
#define CHUNKS 49
#define PIX_PER_CHUNK (HW / CHUNKS)   // 64

// Scratch (allocation-free per harness rules)
__device__ float g_partial[BATCH * CHUNKS * C];
__device__ float g_gate[BATCH * C];

// ---------------------------------------------------------------------------
// Kernel 1: partial GAP sums. grid = (CHUNKS, BATCH), block = 256 (one channel
// per thread). Each iteration the block reads one full 1024B pixel row —
// perfectly coalesced. 64 serial adds per thread, unrolled for MLP.
// ---------------------------------------------------------------------------
__global__ void gap_kernel(const float* __restrict__ x) {
    const int chunk = blockIdx.x;
    const int b     = blockIdx.y;
    const int c     = threadIdx.x;

    const float* xp = x + ((size_t)b * HW + (size_t)chunk * PIX_PER_CHUNK) * C + c;

    float sum = 0.0f;
#pragma unroll 16
    for (int p = 0; p < PIX_PER_CHUNK; ++p) {
        sum += xp[(size_t)p * C];
    }
    g_partial[(b * CHUNKS + chunk) * C + c] = sum;
}

// ---------------------------------------------------------------------------
// Kernel 2: reduce partials -> mean -> w1 -> relu6 -> w2 -> hsigmoid -> gate.
// 32 blocks (one per batch), 256 threads.
// ---------------------------------------------------------------------------
__global__ void fc_kernel(const float* __restrict__ w1,
                          const float* __restrict__ w2) {
    const int b = blockIdx.x;
    const int t = threadIdx.x;

    __shared__ float s[C];
    __shared__ float h[CR];

    // reduce 49 partials for this (b, t) channel
    float sum = 0.0f;
#pragma unroll 7
    for (int k = 0; k < CHUNKS; ++k) {
        sum += g_partial[(b * CHUNKS + k) * C + t];
    }
    s[t] = sum * (1.0f / (float)HW);
    __syncthreads();

    // squeeze: h[r] = relu6( sum_c s[c] * w1[c][r] ), only first 64 threads
    if (t < CR) {
        float acc = 0.0f;
#pragma unroll 8
        for (int c = 0; c < C; ++c) {
            acc += s[c] * w1[c * CR + t];
        }
        h[t] = fminf(fmaxf(acc, 0.0f), 6.0f);
    }
    __syncthreads();

    // excite: v = sum_r h[r] * w2[r][c]; gate = hsigmoid(v)
    float acc = 0.0f;
#pragma unroll
    for (int r = 0; r < CR; ++r) {
        acc += h[r] * w2[r * C + t];
    }
    float gate = fminf(fmaxf(acc + 3.0f, 0.0f), 6.0f) * (1.0f / 6.0f);
    g_gate[b * C + t] = gate;
}

// ---------------------------------------------------------------------------
// Kernel 3: out = x * gate (broadcast over HW). float4 vectorized.
// Total float4s = 32*3136*64 = 6,422,528.
// ---------------------------------------------------------------------------
__global__ void mul_kernel(const float4* __restrict__ x4,
                           float4* __restrict__ out4) {
    const int F4_PER_B   = HW * (C / 4);   // 200704
    const int F4_PER_ROW = C / 4;          // 64
    const size_t total   = (size_t)BATCH * F4_PER_B;

    size_t i = (size_t)blockIdx.x * blockDim.x + threadIdx.x;
    if (i >= total) return;

    const int b  = (int)(i / F4_PER_B);
    const int c4 = (int)(i & (F4_PER_ROW - 1));   // C/4 = 64, power of 2

    float4 xv = x4[i];
    float4 gv = ((const float4*)g_gate)[b * F4_PER_ROW + c4];
    xv.x *= gv.x;
    xv.y *= gv.y;
    xv.z *= gv.z;
    xv.w *= gv.w;
    out4[i] = xv;
}

extern "C" void kernel_launch(void* const* d_in, const int* in_sizes, int n_in,
                              void* d_out, int out_size) {
    const float* x  = (const float*)d_in[0];
    const float* w1 = (const float*)d_in[1];
    const float* w2 = (const float*)d_in[2];
    float* out      = (float*)d_out;

    dim3 gap_grid(CHUNKS, BATCH);
    gap_kernel<<<gap_grid, C>>>(x);

    fc_kernel<<<BATCH, C>>>(w1, w2);

    const size_t total_f4 = (size_t)BATCH * HW * (C / 4);
    const int threads = 256;
    const int blocks  = (int)((total_f4 + threads - 1) / threads);
    mul_kernel<<<blocks, threads>>>((const float4*)x, (float4*)out);
}

// round 2
// speedup vs baseline: 1.0507x; 1.0507x over previous
#include <cuda_runtime.h>

#define BATCH 32
#define HW    3136
#define C     256
#define C4    (C / 4)       // 64
#define CR    64
#define CHUNKS 49
#define PIX_PER_CHUNK (HW / CHUNKS)   // 64

// Scratch (allocation-free per harness rules)
__device__ float g_partial[BATCH * CHUNKS * C];
__device__ float g_gate[BATCH * C];

// ---------------------------------------------------------------------------
// Kernel 1: partial GAP sums with float4 loads.
// grid = (CHUNKS, BATCH), block = 256.
// Thread layout: c4 = tid & 63 (float4 channel group), pr = tid >> 6 (pixel
// subgroup 0..3). Each thread sums 16 pixels (stride 4) with LDG.128, then
// a smem reduce combines the 4 pixel subgroups per channel.
// ---------------------------------------------------------------------------
__global__ void gap_kernel(const float4* __restrict__ x4) {
    const int chunk = blockIdx.x;
    const int b     = blockIdx.y;
    const int tid   = threadIdx.x;
    const int c4    = tid & (C4 - 1);
    const int pr    = tid >> 6;

    const float4* xp = x4 + ((size_t)(b * HW + chunk * PIX_PER_CHUNK + pr)) * C4 + c4;

    float4 s = make_float4(0.f, 0.f, 0.f, 0.f);
#pragma unroll
    for (int p = 0; p < PIX_PER_CHUNK / 4; ++p) {      // 16 iterations
        float4 v = xp[(size_t)p * 4 * C4];
        s.x += v.x; s.y += v.y; s.z += v.z; s.w += v.w;
    }

    __shared__ float4 sm[256];
    sm[tid] = s;
    __syncthreads();

    if (tid < C4) {
        float4 a = sm[tid];
        float4 b1 = sm[tid + 64];
        float4 c1 = sm[tid + 128];
        float4 d1 = sm[tid + 192];
        a.x += b1.x + c1.x + d1.x;
        a.y += b1.y + c1.y + d1.y;
        a.z += b1.z + c1.z + d1.z;
        a.w += b1.w + c1.w + d1.w;
        ((float4*)g_partial)[(b * CHUNKS + chunk) * C4 + tid] = a;
    }
}

// ---------------------------------------------------------------------------
// Kernel 2: reduce partials -> mean -> w1 -> relu6 -> w2 -> hsigmoid -> gate.
// 32 blocks (one per batch), 256 threads.
// ---------------------------------------------------------------------------
__global__ void fc_kernel(const float* __restrict__ w1,
                          const float* __restrict__ w2) {
    const int b = blockIdx.x;
    const int t = threadIdx.x;

    __shared__ float s[C];
    __shared__ float h[CR];

    float sum = 0.0f;
#pragma unroll 7
    for (int k = 0; k < CHUNKS; ++k) {
        sum += g_partial[(b * CHUNKS + k) * C + t];
    }
    s[t] = sum * (1.0f / (float)HW);
    __syncthreads();

    if (t < CR) {
        float acc = 0.0f;
#pragma unroll 8
        for (int c = 0; c < C; ++c) {
            acc += s[c] * w1[c * CR + t];
        }
        h[t] = fminf(fmaxf(acc, 0.0f), 6.0f);
    }
    __syncthreads();

    float acc = 0.0f;
#pragma unroll
    for (int r = 0; r < CR; ++r) {
        acc += h[r] * w2[r * C + t];
    }
    float gate = fminf(fmaxf(acc + 3.0f, 0.0f), 6.0f) * (1.0f / 6.0f);
    g_gate[b * C + t] = gate;
}

// ---------------------------------------------------------------------------
// Kernel 3: out = x * gate. grid = (CHUNKS, BATCH), block = 256.
// Each thread owns one channel group (gate in register) and 16 pixels.
// Streaming stores (__stcs) keep out-writes from evicting x in L2, so the
// x-reads (left hot in L2 by gap_kernel) stay L2 hits.
// ---------------------------------------------------------------------------
__global__ void mul_kernel(const float4* __restrict__ x4,
                           float4* __restrict__ out4) {
    const int chunk = blockIdx.x;
    const int b     = blockIdx.y;
    const int tid   = threadIdx.x;
    const int c4    = tid & (C4 - 1);
    const int pr    = tid >> 6;

    const float4 gv = ((const float4*)g_gate)[b * C4 + c4];

    const size_t base = ((size_t)(b * HW + chunk * PIX_PER_CHUNK + pr)) * C4 + c4;

#pragma unroll
    for (int p = 0; p < PIX_PER_CHUNK / 4; ++p) {      // 16 iterations
        size_t idx = base + (size_t)p * 4 * C4;
        float4 v = x4[idx];
        v.x *= gv.x; v.y *= gv.y; v.z *= gv.z; v.w *= gv.w;
        __stcs(&out4[idx], v);
    }
}

extern "C" void kernel_launch(void* const* d_in, const int* in_sizes, int n_in,
                              void* d_out, int out_size) {
    const float* x  = (const float*)d_in[0];
    const float* w1 = (const float*)d_in[1];
    const float* w2 = (const float*)d_in[2];
    float* out      = (float*)d_out;

    dim3 grid(CHUNKS, BATCH);
    gap_kernel<<<grid, 256>>>((const float4*)x);
    fc_kernel<<<BATCH, C>>>(w1, w2);
    mul_kernel<<<grid, 256>>>((const float4*)x, (float4*)out);
}